// round 2
// baseline (speedup 1.0000x reference)
#include <cuda_runtime.h>
#include <cuda_bf16.h>

#define N_RAYS 131072
#define NS 64
#define NI 128
#define NTOT 192
#define WARPS_PER_BLOCK 8

struct WarpSmem {
    float zv[64];     // z_vals
    float zmid[64];   // 63 midpoints (padded)
    float cdf[64];    // 63 cdf entries (padded)
    float zs[128];    // fine z samples
    float zall[192];  // merged
    float od[8];      // o[0..2], d[0..2]
};

__global__ __launch_bounds__(WARPS_PER_BLOCK * 32)
void nerf_fine_sample_kernel(const float* __restrict__ rays_o,
                             const float* __restrict__ rays_d,
                             const float* __restrict__ z_vals,
                             const float* __restrict__ weights,
                             float* __restrict__ pts_out,
                             float* __restrict__ zall_out) {
    __shared__ WarpSmem ws[WARPS_PER_BLOCK];

    const int warp = threadIdx.x >> 5;
    const int lane = threadIdx.x & 31;
    const int ray  = blockIdx.x * WARPS_PER_BLOCK + warp;
    if (ray >= N_RAYS) return;

    WarpSmem& s = ws[warp];
    const unsigned FULL = 0xffffffffu;

    // ---- 1. load z_vals (64) and ray o/d ----
    const float* zrow = z_vals + (size_t)ray * NS;
    float z0 = zrow[lane];
    float z1 = zrow[lane + 32];
    s.zv[lane]      = z0;
    s.zv[lane + 32] = z1;
    if (lane < 3) {
        s.od[lane]     = rays_o[ray * 3 + lane];
        s.od[4 + lane] = rays_d[ray * 3 + lane];
    }

    // ---- 2. weights -> w (62 entries: weights[1..62]), shfl inclusive scan ----
    const float* wrow = weights + (size_t)ray * NS;
    float wa = (lane < 62)      ? (wrow[1 + lane] + 1e-5f)  : 0.0f;
    float wb = (lane + 32 < 62) ? (wrow[33 + lane] + 1e-5f) : 0.0f;

    float A = wa;
    #pragma unroll
    for (int off = 1; off < 32; off <<= 1) {
        float v = __shfl_up_sync(FULL, A, off);
        if (lane >= off) A += v;
    }
    float total_lo = __shfl_sync(FULL, A, 31);
    float B = wb;
    #pragma unroll
    for (int off = 1; off < 32; off <<= 1) {
        float v = __shfl_up_sync(FULL, B, off);
        if (lane >= off) B += v;
    }
    B += total_lo;
    float total = __shfl_sync(FULL, B, 31);
    float inv_total = 1.0f / total;

    __syncwarp(FULL);
    // zmid: 63 entries
    s.zmid[lane] = 0.5f * (z0 + s.zv[lane + 1]);
    if (lane < 31) s.zmid[lane + 32] = 0.5f * (z1 + s.zv[lane + 33]);

    // cdf[0]=0; cdf[i] = prefix[i-1]*inv_total for i=1..62
    if (lane == 0) s.cdf[0] = 0.0f;
    s.cdf[lane + 1] = A * inv_total;                 // cdf[1..32]
    if (lane < 30) s.cdf[lane + 33] = B * inv_total; // cdf[33..62]
    __syncwarp(FULL);

    // ---- 3. inverse-CDF sampling: 4 u's per lane ----
    #pragma unroll
    for (int t = 0; t < 4; t++) {
        int j = lane + 32 * t;
        float u = (float)j * (1.0f / 127.0f);
        // searchsorted(right) over cdf[0..62]: result in [0, 63]
        int lo = 0, hi = 63;
        #pragma unroll
        for (int it = 0; it < 6; it++) {         // 63 -> 31 -> 15 -> 7 -> 3 -> 1 -> 0
            if (lo < hi) {
                int mid = (lo + hi) >> 1;
                if (s.cdf[mid] <= u) lo = mid + 1; else hi = mid;
            }
        }
        int ind = lo;
        int below = max(ind - 1, 0);
        int above = min(ind, 62);
        float cb = s.cdf[below];
        float ca = s.cdf[above];
        float denom = ca - cb;
        if (denom < 1e-5f) denom = 1.0f;
        float tt = (u - cb) / denom;
        float bb = s.zmid[below];
        float ba = s.zmid[above];
        s.zs[j] = bb + tt * (ba - bb);
    }
    __syncwarp(FULL);

    // ---- 4. rank-merge zv(64) and zs(128), both sorted ----
    // zv elem i -> pos = i + lower_bound(zs, v)
    #pragma unroll
    for (int t = 0; t < 2; t++) {
        int i = lane + 32 * t;
        float v = (t == 0) ? z0 : z1;
        int lo = 0, hi = NI;
        #pragma unroll
        for (int it = 0; it < 8; it++) {        // 128 -> ... -> 1 -> 0 (8 its)
            if (lo < hi) {
                int mid = (lo + hi) >> 1;
                if (s.zs[mid] < v) lo = mid + 1; else hi = mid;
            }
        }
        s.zall[i + lo] = v;
    }
    // zs elem j -> pos = j + upper_bound(zv, v)
    #pragma unroll
    for (int t = 0; t < 4; t++) {
        int j = lane + 32 * t;
        float v = s.zs[j];
        int lo = 0, hi = NS;
        #pragma unroll
        for (int it = 0; it < 7; it++) {        // 64 -> ... -> 1 -> 0 (7 its)
            if (lo < hi) {
                int mid = (lo + hi) >> 1;
                if (s.zv[mid] <= v) lo = mid + 1; else hi = mid;
            }
        }
        s.zall[j + lo] = v;
    }
    __syncwarp(FULL);

    // ---- 5. coalesced writes ----
    float* zout = zall_out + (size_t)ray * NTOT;
    #pragma unroll
    for (int t = 0; t < 6; t++) {
        int m = lane + 32 * t;
        zout[m] = s.zall[m];
    }

    float ox = s.od[0], oy = s.od[1], oz = s.od[2];
    float dx = s.od[4], dy = s.od[5], dz = s.od[6];
    float* pout = pts_out + (size_t)ray * (NTOT * 3);
    #pragma unroll
    for (int t = 0; t < 18; t++) {
        int m = lane + 32 * t;          // 0..575
        int k = m / 3;
        int c = m - 3 * k;
        float z = s.zall[k];
        float o = (c == 0) ? ox : (c == 1) ? oy : oz;
        float d = (c == 0) ? dx : (c == 1) ? dy : dz;
        pout[m] = fmaf(d, z, o);
    }
}

extern "C" void kernel_launch(void* const* d_in, const int* in_sizes, int n_in,
                              void* d_out, int out_size) {
    const float* rays_o  = (const float*)d_in[0];
    const float* rays_d  = (const float*)d_in[1];
    const float* z_vals  = (const float*)d_in[2];
    const float* weights = (const float*)d_in[3];
    float* pts  = (float*)d_out;
    float* zall = (float*)d_out + (size_t)N_RAYS * NTOT * 3;

    dim3 grid(N_RAYS / WARPS_PER_BLOCK);
    dim3 block(WARPS_PER_BLOCK * 32);
    nerf_fine_sample_kernel<<<grid, block>>>(rays_o, rays_d, z_vals, weights, pts, zall);
}

// round 4
// speedup vs baseline: 1.5629x; 1.5629x over previous
#include <cuda_runtime.h>
#include <cuda_bf16.h>

#define N_RAYS 131072
#define NS 64
#define NI 128
#define NTOT 192
#define WARPS_PER_BLOCK 8

struct alignas(16) WarpSmem {
    float zv[64];     // z_vals
    float zmid[64];   // 63 midpoints (padded)
    float cdf[64];    // 63 cdf entries + sentinel at [63]
    float zs[128];    // fine z samples
    float zall[192];  // merged  (16B-aligned)
    float od[8];      // o[0..2], d[0..2]
};

__global__ __launch_bounds__(WARPS_PER_BLOCK * 32)
void nerf_fine_sample_kernel(const float* __restrict__ rays_o,
                             const float* __restrict__ rays_d,
                             const float* __restrict__ z_vals,
                             const float* __restrict__ weights,
                             float* __restrict__ pts_out,
                             float* __restrict__ zall_out) {
    __shared__ WarpSmem ws[WARPS_PER_BLOCK];

    const int warp = threadIdx.x >> 5;
    const int lane = threadIdx.x & 31;
    const int ray  = blockIdx.x * WARPS_PER_BLOCK + warp;

    WarpSmem& s = ws[warp];
    const unsigned FULL = 0xffffffffu;

    // ---- 1. load z_vals (64) and ray o/d ----
    const float* zrow = z_vals + (size_t)ray * NS;
    float z0 = zrow[lane];
    float z1 = zrow[lane + 32];
    s.zv[lane]      = z0;
    s.zv[lane + 32] = z1;
    if (lane < 3) {
        s.od[lane]     = rays_o[ray * 3 + lane];
        s.od[4 + lane] = rays_d[ray * 3 + lane];
    }

    // ---- 2. weights -> w (62 entries: weights[1..62]), shfl inclusive scan ----
    const float* wrow = weights + (size_t)ray * NS;
    float wa = (lane < 62)      ? (wrow[1 + lane] + 1e-5f)  : 0.0f;
    float wb = (lane + 32 < 62) ? (wrow[33 + lane] + 1e-5f) : 0.0f;

    float A = wa;
    #pragma unroll
    for (int off = 1; off < 32; off <<= 1) {
        float v = __shfl_up_sync(FULL, A, off);
        if (lane >= off) A += v;
    }
    float total_lo = __shfl_sync(FULL, A, 31);
    float B = wb;
    #pragma unroll
    for (int off = 1; off < 32; off <<= 1) {
        float v = __shfl_up_sync(FULL, B, off);
        if (lane >= off) B += v;
    }
    B += total_lo;
    float total = __shfl_sync(FULL, B, 31);
    float inv_total = 1.0f / total;

    __syncwarp(FULL);
    // pick up o/d early (hide LDS latency behind the rest)
    float ox = s.od[0], oy = s.od[1], oz = s.od[2];
    float dx = s.od[4], dy = s.od[5], dz = s.od[6];

    // zmid: 63 entries
    s.zmid[lane] = 0.5f * (z0 + s.zv[lane + 1]);
    if (lane < 31) s.zmid[lane + 32] = 0.5f * (z1 + s.zv[lane + 33]);

    // cdf[0]=0; cdf[i]=prefix[i-1]*inv_total for i=1..62; cdf[63]=sentinel (> any u)
    if (lane == 0) s.cdf[0] = 0.0f;
    s.cdf[lane + 1] = A * inv_total;                 // cdf[1..32]
    if (lane < 30) s.cdf[lane + 33] = B * inv_total; // cdf[33..62]
    if (lane == 31) s.cdf[63] = 2.0f;                // sentinel
    __syncwarp(FULL);

    // ---- 3. inverse-CDF sampling: 4 u's per lane, branchless search over 64 ----
    // count of cdf entries <= u is at most 63 (sentinel > u) -> fits step sum 63
    const float lu = (float)lane * (1.0f / 127.0f);
    #pragma unroll
    for (int t = 0; t < 4; t++) {
        float u = lu + (float)t * (32.0f / 127.0f);
        int ind = 0;
        #pragma unroll
        for (int step = 32; step > 0; step >>= 1)
            if (s.cdf[ind + step - 1] <= u) ind += step;
        // cdf[0]=0 <= u always -> ind >= 1
        int below = ind - 1;
        int above = min(ind, 62);
        float cb = s.cdf[below];
        float ca = s.cdf[above];
        float denom = ca - cb;
        if (denom < 1e-5f) denom = 1.0f;
        float tt = (u - cb) / denom;
        float bb = s.zmid[below];
        float ba = s.zmid[above];
        s.zs[lane + 32 * t] = bb + tt * (ba - bb);
    }
    __syncwarp(FULL);

    // ---- 4. rank-merge zv(64) and zs(128), both sorted, branchless ----
    // zv elem i -> pos = i + #{zs < v}. Count can be 0..128; loop covers 0..127,
    // final conditional increment covers the count==128 case (always hit by zv[63]).
    #pragma unroll
    for (int t = 0; t < 2; t++) {
        int i = lane + 32 * t;
        float v = (t == 0) ? z0 : z1;
        int r = 0;
        #pragma unroll
        for (int step = 64; step > 0; step >>= 1)
            if (s.zs[r + step - 1] < v) r += step;
        if (s.zs[r] < v) r++;          // r<=127 here, read valid; exact when count==128
        s.zall[i + r] = v;
    }
    // zs elem j -> pos = j + #{zv <= v}. Count <= 63 (zv[63] > all zs) -> fits sum 63.
    #pragma unroll
    for (int t = 0; t < 4; t++) {
        int j = lane + 32 * t;
        float v = s.zs[j];
        int r = 0;
        #pragma unroll
        for (int step = 32; step > 0; step >>= 1)
            if (s.zv[r + step - 1] <= v) r += step;
        s.zall[j + r] = v;
    }
    __syncwarp(FULL);

    // ---- 5a. z_all out: 48 float4 per ray, coalesced ----
    const float4* z4 = (const float4*)s.zall;
    float4* zo4 = (float4*)(zall_out + (size_t)ray * NTOT);
    zo4[lane] = z4[lane];
    if (lane < 16) zo4[32 + lane] = z4[32 + lane];

    // ---- 5b. pts out: lane-constant (k, o, d) triples, 6 groups of 96 ----
    int k0 = lane / 3,  c0 = lane - 3 * k0;
    int p1 = lane + 32;
    int k1 = p1 / 3,    c1 = p1 - 3 * k1;
    int p2 = lane + 64;
    int k2 = p2 / 3,    c2 = p2 - 3 * k2;
    float o0 = (c0 == 0) ? ox : (c0 == 1) ? oy : oz;
    float d0 = (c0 == 0) ? dx : (c0 == 1) ? dy : dz;
    float o1 = (c1 == 0) ? ox : (c1 == 1) ? oy : oz;
    float d1 = (c1 == 0) ? dx : (c1 == 1) ? dy : dz;
    float o2 = (c2 == 0) ? ox : (c2 == 1) ? oy : oz;
    float d2 = (c2 == 0) ? dx : (c2 == 1) ? dy : dz;

    float* pout = pts_out + (size_t)ray * (NTOT * 3);
    #pragma unroll
    for (int g = 0; g < 6; g++) {
        const float* zg = s.zall + 32 * g;
        float* pg = pout + 96 * g;
        pg[lane] = fmaf(d0, zg[k0], o0);
        pg[p1]   = fmaf(d1, zg[k1], o1);
        pg[p2]   = fmaf(d2, zg[k2], o2);
    }
}

extern "C" void kernel_launch(void* const* d_in, const int* in_sizes, int n_in,
                              void* d_out, int out_size) {
    const float* rays_o  = (const float*)d_in[0];
    const float* rays_d  = (const float*)d_in[1];
    const float* z_vals  = (const float*)d_in[2];
    const float* weights = (const float*)d_in[3];
    float* pts  = (float*)d_out;
    float* zall = (float*)d_out + (size_t)N_RAYS * NTOT * 3;

    dim3 grid(N_RAYS / WARPS_PER_BLOCK);
    dim3 block(WARPS_PER_BLOCK * 32);
    nerf_fine_sample_kernel<<<grid, block>>>(rays_o, rays_d, z_vals, weights, pts, zall);
}